// round 9
// baseline (speedup 1.0000x reference)
#include <cuda_runtime.h>

// XAJ hydrological scan: T=730, B=16384, evap MLP 8->16->8->1.
// Round 9: R1's exact structure (the only form that holds 242 regs / 337us;
// every variant that reached 254+ regs lost 10-40%). Changes are strictly
// subtractive/scheduling: (1) unroll 4 so ptxas interleaves the independent
// forcing-FMAs + LDS of later steps into each step's serial MUFU tail,
// (2) IEEE div -> MUFU.RCP (fdividef), (3) powf/expf -> explicit lg2/ex2
// with the w0c-dependent lg2 issued at step top. No new persistent state.
#define T_STEPS 730
#define NBASIN  16384
#define NH1     16
#define NH2     8
#define EPSV    1e-5f

// MUFU.EX2 / MUFU.LG2 — the ops __expf/__powf decompose into.
__device__ __forceinline__ float ex2f(float x) {
    float r; asm("ex2.approx.f32 %0, %1;" : "=f"(r) : "f"(x)); return r;
}
__device__ __forceinline__ float lg2f(float x) {
    float r; asm("lg2.approx.f32 %0, %1;" : "=f"(r) : "f"(x)); return r;
}

__global__ __launch_bounds__(128, 1)
void xaj_dpl9_kernel(const float2* __restrict__ p_and_e,
                     const float*  __restrict__ kc_,
                     const float*  __restrict__ um_,
                     const float*  __restrict__ lm_,
                     const float*  __restrict__ dm_,
                     const float*  __restrict__ b_,
                     const float*  __restrict__ im_,
                     const float*  __restrict__ c_,
                     const float*  __restrict__ w0_,
                     const float*  __restrict__ W1,
                     const float*  __restrict__ b1,
                     const float*  __restrict__ W2,
                     const float*  __restrict__ b2,
                     const float*  __restrict__ W3,
                     const float*  __restrict__ b3,
                     float4*       __restrict__ out)
{
    // W2 [16,8] broadcast from shared via LDS.128 (conflict-free broadcast).
    __shared__ float sW2[NH1 * NH2];
    if (threadIdx.x < NH1 * NH2) sW2[threadIdx.x] = W2[threadIdx.x];
    __syncthreads();

    const int bas = blockIdx.x * blockDim.x + threadIdx.x;

    // Per-basin time-invariant parameters (R1 layout)
    const float kc = kc_[bas];
    const float um = um_[bas];
    const float lm = lm_[bas];
    const float dm = dm_[bas];
    const float bb = b_[bas];
    const float im = im_[bas];
    const float cc = c_[bas];
    float w = w0_[bas];

    const float wm      = um + lm + dm;
    const float one_b   = 1.0f + bb;
    const float wmm     = wm * one_b;
    const float inv_b1  = 1.0f / one_b;
    const float inv_wm  = 1.0f / wm;
    const float inv_wmm = 1.0f / wmm;
    const float wm_eps  = wm - EPSV;

    // Fold constant features (kc,um,lm,dm,c) of layer 1 into h1b once.
    float h1b[NH1], w5[NH1], w6[NH1], w7[NH1];
#pragma unroll
    for (int i = 0; i < NH1; i++) {
        float r0 = W1[0 * NH1 + i];
        float r1 = W1[1 * NH1 + i];
        float r2 = W1[2 * NH1 + i];
        float r3 = W1[3 * NH1 + i];
        float r4 = W1[4 * NH1 + i];
        h1b[i] = b1[i] + kc * r0 + um * r1 + lm * r2 + dm * r3 + cc * r4;
        w5[i] = W1[5 * NH1 + i];
        w6[i] = W1[6 * NH1 + i];
        w7[i] = W1[7 * NH1 + i];
    }
    float rb2[NH2], rw3[NH2];
#pragma unroll
    for (int k = 0; k < NH2; k++) { rb2[k] = b2[k]; rw3[k] = W3[k]; }
    const float rb3 = b3[0];

    // Distance-2 prefetch of forcing data (as in R1).
    const float2* pe_ptr = p_and_e + bas;
    float2 pe_a = pe_ptr[0];
    float2 pe_b = pe_ptr[NBASIN];

    float4* out_ptr = out + bas;

#pragma unroll 4
    for (int t = 0; t < T_STEPS; t++) {
        const float2 pe = pe_a;
        pe_a = pe_b;
        if (t + 2 < T_STEPS) pe_b = pe_ptr[(size_t)(t + 2) * NBASIN];

        const float prcp = fmaxf(pe.x, 0.0f);
        const float pet  = fmaxf(pe.y, 0.0f);
        const float kpet = kc * pet;
        const float w0c  = fminf(fmaxf(w, 0.0f), wm_eps);

        // w0c-dependent MUFU chain starts immediately (off the MLP path).
        const float frac   = fminf(fmaxf(fmaf(-w0c, inv_wm, 1.0f), EPSV), 1.0f);
        const float a_xaj  = wmm * (1.0f - ex2f(inv_b1 * lg2f(frac)));
        const float r_base = w0c - wm;               // r_full = pe_net + r_base

        // ---- evap MLP: layer 1 (folded constants + 3 live features) ----
        float h[NH1];
#pragma unroll
        for (int i = 0; i < NH1; i++) {
            float hh = h1b[i] + w0c * w5[i] + prcp * w6[i] + pet * w7[i];
            h[i] = fmaxf(hh, 0.0f);
        }

        // ---- layer 2: 16x8 matvec, 8 independent accumulators (R1 form) ----
        float a0 = rb2[0], a1 = rb2[1], a2 = rb2[2], a3 = rb2[3];
        float a4 = rb2[4], a5 = rb2[5], a6 = rb2[6], a7 = rb2[7];
#pragma unroll
        for (int j = 0; j < NH1; j++) {
            const float4 wA = *reinterpret_cast<const float4*>(&sW2[j * NH2]);
            const float4 wB = *reinterpret_cast<const float4*>(&sW2[j * NH2 + 4]);
            const float hj = h[j];
            a0 = fmaf(hj, wA.x, a0); a1 = fmaf(hj, wA.y, a1);
            a2 = fmaf(hj, wA.z, a2); a3 = fmaf(hj, wA.w, a3);
            a4 = fmaf(hj, wB.x, a4); a5 = fmaf(hj, wB.y, a5);
            a6 = fmaf(hj, wB.z, a6); a7 = fmaf(hj, wB.w, a7);
        }

        // ---- layer 3 (scalar tree) ----
        float y0 = rb3 + fmaxf(a0, 0.0f) * rw3[0];
        float y1 = fmaxf(a1, 0.0f) * rw3[1];
        float y2 = fmaxf(a2, 0.0f) * rw3[2];
        float y3 = fmaxf(a3, 0.0f) * rw3[3];
        y0 = fmaf(fmaxf(a4, 0.0f), rw3[4], y0);
        y1 = fmaf(fmaxf(a5, 0.0f), rw3[5], y1);
        y2 = fmaf(fmaxf(a6, 0.0f), rw3[6], y2);
        y3 = fmaf(fmaxf(a7, 0.0f), rw3[7], y3);
        const float y = (y0 + y1) + (y2 + y3);

        // sigmoid * kc * pet (MUFU EX2 + MUFU RCP via fdividef)
        const float ex = ex2f(-1.442695040888963f * y);
        const float e  = __fdividef(kpet, 1.0f + ex);

        // ---- XAJ water balance ----
        const float pd     = prcp - e;
        const float pe_net = fmaxf(pd, 0.0f);
        const float resid  = fminf(fmaxf(fmaf(-(pe_net + a_xaj), inv_wmm, 1.0f), 0.0f), 1.0f);
        // resid==0 exactly when pe_net + a >= wmm; ex2(one_b*lg2(0)) = 0,
        // so this is branchlessly identical to the reference's where().
        const float rp  = ex2f(one_b * lg2f(resid));
        const float r   = fmaxf(pe_net + r_base + wm * rp, 0.0f);
        const float rim = pe_net * im;

        w = fminf(fmaxf(w0c + pd - r, 0.0f), wm_eps);

        out_ptr[0] = make_float4(r, rim, e, pe_net);
        out_ptr += NBASIN;
    }
}

extern "C" void kernel_launch(void* const* d_in, const int* in_sizes, int n_in,
                              void* d_out, int out_size)
{
    (void)in_sizes; (void)n_in; (void)out_size;
    const float2* p_and_e = (const float2*)d_in[0];
    const float*  kc = (const float*)d_in[1];
    const float*  um = (const float*)d_in[2];
    const float*  lm = (const float*)d_in[3];
    const float*  dm = (const float*)d_in[4];
    const float*  b  = (const float*)d_in[5];
    const float*  im = (const float*)d_in[6];
    const float*  c  = (const float*)d_in[7];
    const float*  w0 = (const float*)d_in[8];
    const float*  W1 = (const float*)d_in[9];
    const float*  b1 = (const float*)d_in[10];
    const float*  W2 = (const float*)d_in[11];
    const float*  b2 = (const float*)d_in[12];
    const float*  W3 = (const float*)d_in[13];
    const float*  b3 = (const float*)d_in[14];
    float4* out = (float4*)d_out;

    // 16384 threads = 512 warps: exactly 4 warps/SM, 1 per SMSP on 128 SMs —
    // the balanced optimum for B=16384 (proven across rounds 1-8).
    xaj_dpl9_kernel<<<128, 128>>>(p_and_e, kc, um, lm, dm, b, im, c, w0,
                                  W1, b1, W2, b2, W3, b3, out);
}